// round 1
// baseline (speedup 1.0000x reference)
#include <cuda_runtime.h>

// LinearInterpolation: out[b, p-1, :] = lerp(value[b, seg, :], value[b, seg+1, :], t)
// for p in [idx0+1, idx0+m], seg = searchsorted(index, p, 'left') - 1.
//
// Pure HBM-streaming kernel: 27 MB read + 101 MB write. Strategy:
//  - per-block shared precompute of (seg, t) for all m positions
//  - one thread per output float2, blockDim = (m, ROWS_PER_BLOCK)
//  - coalesced float2 stores; value-row loads served by L1 (shared within block)

#define ROWS_PER_BLOCK 8
#define MAX_M 64  // m = index[last]-index[0]; 48 for this problem

__global__ void LinearInterpolation_20907900797406_kernel(
    const int* __restrict__ index,
    const float2* __restrict__ value,   // [batch, nk] of float2
    float2* __restrict__ out,           // [batch, m] of float2
    int batch, int nk, int m)
{
    __shared__ int   s_seg[MAX_M];
    __shared__ float s_t[MAX_M];

    const int tx = threadIdx.x;  // p-index, 0..m-1

    if (threadIdx.y == 0 && tx < m) {
        const int p = index[0] + 1 + tx;
        int seg = 0;
        #pragma unroll 4
        for (int i = 1; i < nk; ++i) {
            if (index[i] < p) seg = i;
        }
        const float x0 = (float)index[seg];
        const float x1 = (float)index[seg + 1];
        s_seg[tx] = seg;
        s_t[tx]   = ((float)p - x0) / (x1 - x0);
    }
    __syncthreads();

    const int b = blockIdx.x * ROWS_PER_BLOCK + threadIdx.y;
    if (b >= batch) return;

    const int   seg = s_seg[tx];
    const float t   = s_t[tx];

    const float2 v0 = value[(long long)b * nk + seg];
    const float2 v1 = value[(long long)b * nk + seg + 1];

    float2 r;
    r.x = fmaf(v1.x - v0.x, t, v0.x);
    r.y = fmaf(v1.y - v0.y, t, v0.y);

    out[(long long)b * m + tx] = r;
}

extern "C" void kernel_launch(void* const* d_in, const int* in_sizes, int n_in,
                              void* d_out, int out_size)
{
    const int*   index = (const int*)d_in[0];
    const float* value = (const float*)d_in[1];
    float*       outp  = (float*)d_out;

    const int nk    = in_sizes[0];                   // 13
    const int batch = in_sizes[1] / (nk * 2);        // 262144
    const int m     = out_size / (batch * 2);        // 48

    dim3 block(m, ROWS_PER_BLOCK);
    dim3 grid((batch + ROWS_PER_BLOCK - 1) / ROWS_PER_BLOCK);

    LinearInterpolation_20907900797406_kernel<<<grid, block>>>(
        index, (const float2*)value, (float2*)outp, batch, nk, m);
}

// round 2
// speedup vs baseline: 1.9641x; 1.9641x over previous
#include <cuda_runtime.h>

// LinearInterpolation, streaming-optimized:
//   out[b, p, :] = lerp(value[b, seg(p), :], value[b, seg(p)+1, :], t(p))
// nk=13 knots, m=48 positions, batch=262144.
//
// Block of 256 threads processes ROWS=32 batch rows:
//   1. coalesced LDG.128 of the 32x26-float input slab into smem
//   2. seg/t precomputed once into smem
//   3. each thread emits 3 float4 outputs, iteration-interleaved so every
//      STG.128 warp transaction is fully coalesced (output slab is one
//      contiguous 12288B range per block)
// Divergent per-segment gathers are LDS.64 from smem instead of LDG.

#define THREADS 256
#define ROWS    32
#define MAX_M   64
#define MAX_NK  32

__global__ __launch_bounds__(THREADS)
void LinearInterpolation_20907900797406_kernel(
    const int*    __restrict__ index,
    const float4* __restrict__ value4,   // input viewed as float4
    float4*       __restrict__ out4,     // output viewed as float4
    int batch, int nk, int m)
{
    extern __shared__ float s_in[];              // ROWS * FR floats
    __shared__ int   s_seg[MAX_M];
    __shared__ float s_t[MAX_M];

    const int tid = threadIdx.x;
    const int FR  = nk * 2;                      // floats per input row (26)
    const int row0 = blockIdx.x * ROWS;
    const int nrows = min(ROWS, batch - row0);

    // ---- seg / t precompute (48 entries) ----
    if (tid < m) {
        const int p = index[0] + 1 + tid;
        int seg = 0;
        #pragma unroll 4
        for (int i = 1; i < nk; ++i)
            if (index[i] < p) seg = i;
        const float x0 = (float)index[seg];
        const float x1 = (float)index[seg + 1];
        s_seg[tid] = seg;
        s_t[tid]   = ((float)p - x0) / (x1 - x0);
    }

    // ---- coalesced input stage: nrows*FR floats, base is 16B-aligned
    //      (row0*FR*4 bytes; FR=26, ROWS=32 -> 3328B per block) ----
    {
        const int nfloats = nrows * FR;
        const int nf4     = nfloats >> 2;        // FR even, ROWS mult of 2 -> exact
        const long long base4 = (long long)row0 * FR >> 2;
        float4* s4 = reinterpret_cast<float4*>(s_in);
        for (int i = tid; i < nf4; i += THREADS)
            s4[i] = value4[base4 + i];
        // tail floats (if nfloats not multiple of 4 — not the case here, but safe)
        const float* vf = reinterpret_cast<const float*>(value4);
        for (int i = (nf4 << 2) + tid; i < nfloats; i += THREADS)
            s_in[i] = vf[(long long)row0 * FR + i];
    }
    __syncthreads();

    // ---- compute + coalesced float4 stores ----
    // output slab: nrows * (2*m) floats = nrows * (m/2) float4, contiguous.
    const int f4_per_row = m >> 1;               // 24
    const int nf4_out    = nrows * f4_per_row;   // 768
    const long long obase4 = (long long)row0 * f4_per_row;

    for (int i = tid; i < nf4_out; i += THREADS) {
        const int row = i / f4_per_row;
        const int pp  = i - row * f4_per_row;    // float4 index within row
        const int p0  = pp << 1;
        const int p1  = p0 + 1;

        const float* r = s_in + row * FR;

        const int   sA = s_seg[p0];
        const float tA = s_t[p0];
        const float2 a0 = *reinterpret_cast<const float2*>(r + 2 * sA);
        const float2 a1 = *reinterpret_cast<const float2*>(r + 2 * sA + 2);

        const int   sB = s_seg[p1];
        const float tB = s_t[p1];
        const float2 b0 = *reinterpret_cast<const float2*>(r + 2 * sB);
        const float2 b1 = *reinterpret_cast<const float2*>(r + 2 * sB + 2);

        float4 o;
        o.x = fmaf(a1.x - a0.x, tA, a0.x);
        o.y = fmaf(a1.y - a0.y, tA, a0.y);
        o.z = fmaf(b1.x - b0.x, tB, b0.x);
        o.w = fmaf(b1.y - b0.y, tB, b0.y);

        out4[obase4 + i] = o;
    }
}

extern "C" void kernel_launch(void* const* d_in, const int* in_sizes, int n_in,
                              void* d_out, int out_size)
{
    const int*   index = (const int*)d_in[0];
    const float* value = (const float*)d_in[1];

    const int nk    = in_sizes[0];                   // 13
    const int batch = in_sizes[1] / (nk * 2);        // 262144
    const int m     = out_size / (batch * 2);        // 48

    const int grid = (batch + ROWS - 1) / ROWS;
    const int smem = ROWS * nk * 2 * sizeof(float);  // 3328 B

    LinearInterpolation_20907900797406_kernel<<<grid, THREADS, smem>>>(
        index,
        reinterpret_cast<const float4*>(value),
        reinterpret_cast<float4*>(d_out),
        batch, nk, m);
}

// round 3
// speedup vs baseline: 2.2845x; 1.1631x over previous
#include <cuda_runtime.h>

// LinearInterpolation specialized for nk=13 knots, m=48 positions.
//   out[b, p, :] = lerp(value[b, seg(p), :], value[b, seg(p)+1, :], t(p))
//
// Issue-bound optimization round:
//  - blockDim (24, 8): threadIdx.x = output-pair index pp (constant per thread)
//    -> seg/t hoisted to setup, no integer division anywhere in hot loop
//  - ROWS=64 rows per block, 8 fully-unrolled iterations with immediate offsets
//  - packed fma.rn.f32x2 for the lerp (ptxas never auto-fuses these)
//  - hot loop per float4 output: 4x LDS.64 + 4x FFMA2 + 1x STG.128

typedef unsigned long long ull;

__device__ __forceinline__ ull fma2(ull a, ull b, ull c) {
    ull d;
    asm("fma.rn.f32x2 %0, %1, %2, %3;" : "=l"(d) : "l"(a), "l"(b), "l"(c));
    return d;
}
__device__ __forceinline__ ull pack2(float lo, float hi) {
    ull d;
    asm("mov.b64 %0, {%1, %2};" : "=l"(d) : "f"(lo), "f"(hi));
    return d;
}

// ---- specialized path: nk=13, m=48 ----
#define NK    13
#define FR    26          // floats per input row
#define FR2   13          // ull (float2) per input row
#define M     48
#define TXc   24          // float4 outputs per row
#define TYc   8
#define ROWS  64
#define ITERS (ROWS / TYc)

__global__ __launch_bounds__(TXc * TYc)
void lerp_spec_kernel(const int*    __restrict__ index,
                      const float4* __restrict__ v4,
                      float4*       __restrict__ out4,
                      int batch)
{
    __shared__ float s_in[ROWS * FR];     // 6656 B
    __shared__ int   s_seg[M];
    __shared__ float s_t[M];

    const int tx  = threadIdx.x;          // 0..23
    const int ty  = threadIdx.y;          // 0..7
    const int tid = ty * TXc + tx;        // 0..191
    const int row0 = blockIdx.x * ROWS;
    const int nrows = min(ROWS, batch - row0);

    // seg / t precompute (once per block)
    if (tid < M) {
        const int p = index[0] + 1 + tid;
        int seg = 0;
        #pragma unroll
        for (int i = 1; i < NK; ++i)
            if (index[i] < p) seg = i;
        const float x0 = (float)index[seg];
        const float x1 = (float)index[seg + 1];
        s_seg[tid] = seg;
        s_t[tid]   = ((float)p - x0) / (x1 - x0);
    }

    // coalesced stage-in: nrows * FR floats (64*26 = 1664 -> 416 float4)
    {
        const int nfloats = nrows * FR;
        const int nf4     = nfloats >> 2;
        const long long base4 = ((long long)row0 * FR) >> 2;   // exact: ROWS*FR%4==0
        float4* s4 = reinterpret_cast<float4*>(s_in);
        #pragma unroll 3
        for (int i = tid; i < nf4; i += TXc * TYc)
            s4[i] = v4[base4 + i];
        const float* vf = reinterpret_cast<const float*>(v4);
        for (int i = (nf4 << 2) + tid; i < nfloats; i += TXc * TYc)
            s_in[i] = vf[(long long)row0 * FR + i];
    }
    __syncthreads();

    // per-thread invariants
    const int p0 = tx << 1;
    const int sA = s_seg[p0];
    const int sB = s_seg[p0 + 1];
    const ull ttA = pack2(s_t[p0],     s_t[p0]);
    const ull ttB = pack2(s_t[p0 + 1], s_t[p0 + 1]);
    const ull M1  = 0xBF800000BF800000ULL;        // (-1.0f, -1.0f)

    const ull* rbase = reinterpret_cast<const ull*>(s_in) + ty * FR2;
    long long ob = (long long)(row0 + ty) * TXc + tx;

    #pragma unroll
    for (int k = 0; k < ITERS; ++k) {
        const int row = ty + k * TYc;
        if (row >= nrows) break;

        const ull* r = rbase + k * (TYc * FR2);
        const ull a0 = r[sA], a1 = r[sA + 1];
        const ull b0 = r[sB], b1 = r[sB + 1];

        const ull oA = fma2(fma2(a0, M1, a1), ttA, a0);   // a0 + (a1-a0)*t
        const ull oB = fma2(fma2(b0, M1, b1), ttB, b0);

        float4 o;
        asm("mov.b64 {%0, %1}, %2;" : "=f"(o.x), "=f"(o.y) : "l"(oA));
        asm("mov.b64 {%0, %1}, %2;" : "=f"(o.z), "=f"(o.w) : "l"(oB));
        out4[ob + (long long)k * (TYc * TXc)] = o;
    }
}

// ---- generic fallback (any nk/m, m even) — round-2 style ----
#define GTHREADS 256
#define GROWS    32
__global__ __launch_bounds__(GTHREADS)
void lerp_generic_kernel(const int* __restrict__ index,
                         const float* __restrict__ value,
                         float2* __restrict__ out2,
                         int batch, int nk, int m)
{
    __shared__ int   s_seg[256];
    __shared__ float s_t[256];
    const int tid = threadIdx.x;
    if (tid < m) {
        const int p = index[0] + 1 + tid;
        int seg = 0;
        for (int i = 1; i < nk; ++i)
            if (index[i] < p) seg = i;
        const float x0 = (float)index[seg];
        const float x1 = (float)index[seg + 1];
        s_seg[tid] = seg;
        s_t[tid]   = ((float)p - x0) / (x1 - x0);
    }
    __syncthreads();
    const long long total = (long long)batch * m;
    for (long long i = (long long)blockIdx.x * GTHREADS + tid; i < total;
         i += (long long)gridDim.x * GTHREADS) {
        const int pp = (int)(i % m);
        const long long b = i / m;
        const int seg = s_seg[pp];
        const float t = s_t[pp];
        const float2* r = reinterpret_cast<const float2*>(value) + b * nk;
        const float2 v0 = r[seg], v1 = r[seg + 1];
        float2 o;
        o.x = fmaf(v1.x - v0.x, t, v0.x);
        o.y = fmaf(v1.y - v0.y, t, v0.y);
        out2[i] = o;
    }
}

extern "C" void kernel_launch(void* const* d_in, const int* in_sizes, int n_in,
                              void* d_out, int out_size)
{
    const int*   index = (const int*)d_in[0];
    const float* value = (const float*)d_in[1];

    const int nk    = in_sizes[0];                   // 13
    const int batch = in_sizes[1] / (nk * 2);        // 262144
    const int m     = out_size / (batch * 2);        // 48

    if (nk == NK && m == M) {
        const int grid = (batch + ROWS - 1) / ROWS;  // 4096
        dim3 block(TXc, TYc);
        lerp_spec_kernel<<<grid, block>>>(
            index,
            reinterpret_cast<const float4*>(value),
            reinterpret_cast<float4*>(d_out),
            batch);
    } else {
        const long long total = (long long)batch * m;
        int grid = (int)min((total + GTHREADS - 1) / GTHREADS, (long long)65535 * 8);
        lerp_generic_kernel<<<grid, GTHREADS>>>(
            index, value, reinterpret_cast<float2*>(d_out), batch, nk, m);
    }
}